// round 1
// baseline (speedup 1.0000x reference)
#include <cuda_runtime.h>

#define NBINS 64
#define ROW_LEN 8192
#define WARPS_PER_BLOCK 4
#define BLOCK_THREADS (WARPS_PER_BLOCK * 32)

// Per-thread-private histograms in shared memory:
//   priv[warp][bin][lane]  -> smem word index (within warp slab) = bin*32 + lane
//   bank = (bin*32 + lane) % 32 = lane  => always conflict-free, never an
//   address collision (each lane only touches its own column).
__global__ __launch_bounds__(BLOCK_THREADS, 7)
void hist_rows_kernel(const float* __restrict__ x, float* __restrict__ out) {
    __shared__ unsigned int priv[WARPS_PER_BLOCK][NBINS][32];

    const int warp = threadIdx.x >> 5;
    const int lane = threadIdx.x & 31;
    const int row  = blockIdx.x * WARPS_PER_BLOCK + warp;

    unsigned int (*h)[32] = priv[warp];

    // Zero this lane's private column (per-lane private: no sync needed before use).
    #pragma unroll
    for (int b = 0; b < NBINS; b++) h[b][lane] = 0u;

    const float4* __restrict__ xr =
        (const float4*)(x + (size_t)row * ROW_LEN);

    const float scale = 64.0f / 6.0f;   // NBINS / (VMAX - VMIN), fp32-rounded like ref

    // 8192 floats = 2048 float4 per row; 64 float4 per lane; unroll 4 for MLP.
    #pragma unroll 1
    for (int it = 0; it < (ROW_LEN / 4) / 32; it += 4) {
        float4 v0 = xr[(it + 0) * 32 + lane];
        float4 v1 = xr[(it + 1) * 32 + lane];
        float4 v2 = xr[(it + 2) * 32 + lane];
        float4 v3 = xr[(it + 3) * 32 + lane];

        #pragma unroll
        for (int k = 0; k < 4; k++) {
            float4 v = (k == 0) ? v0 : (k == 1) ? v1 : (k == 2) ? v2 : v3;
            float f[4] = {v.x, v.y, v.z, v.w};
            #pragma unroll
            for (int j = 0; j < 4; j++) {
                // Exactly the reference fp32 sequence: (x - VMIN) then * scale,
                // floor (round toward -inf), clamp to [0, 63].
                int b = __float2int_rd(__fmul_rn(__fadd_rn(f[j], 3.0f), scale));
                b = max(0, min(NBINS - 1, b));
                atomicAdd(&h[b][lane], 1u);   // fire-and-forget, bank = lane
            }
        }
    }

    __syncwarp();

    // Reduce: lane l owns bins l and l+32. Rotated read (t+lane)&31 keeps the
    // bank index distinct per lane on every step.
    unsigned int s0 = 0, s1 = 0;
    #pragma unroll
    for (int t = 0; t < 32; t++) {
        int tt = (t + lane) & 31;
        s0 += h[lane][tt];
        s1 += h[lane + 32][tt];
    }

    float* o = out + (size_t)row * NBINS;
    const float inv_n = 1.0f / (float)ROW_LEN;
    o[lane]      = (float)s0 * inv_n;
    o[lane + 32] = (float)s1 * inv_n;
}

extern "C" void kernel_launch(void* const* d_in, const int* in_sizes, int n_in,
                              void* d_out, int out_size) {
    const float* x = (const float*)d_in[0];
    float* out = (float*)d_out;

    int nrows = in_sizes[0] / ROW_LEN;            // 4096
    int grid = nrows / WARPS_PER_BLOCK;           // 1024 blocks, 1 warp per row

    hist_rows_kernel<<<grid, BLOCK_THREADS>>>(x, out);
}

// round 2
// speedup vs baseline: 1.1740x; 1.1740x over previous
#include <cuda_runtime.h>

#define NBINS 64
#define ROW_LEN 8192
#define WARPS_PER_BLOCK 8          // 8 warps = 4 rows per block (2 warps/row)
#define ROWS_PER_BLOCK (WARPS_PER_BLOCK / 2)
#define BLOCK_THREADS (WARPS_PER_BLOCK * 32)
#define HALF_ROW (ROW_LEN / 2)     // 4096 elements per warp

// One 8KB histogram slab per ROW, shared by the row's 2 warps.
//   priv[pair][bin][lane]: bank = lane -> conflict-free.
//   Within a warp each lane owns its column (no intra-warp races);
//   the two warps of a pair may collide on (bin,lane) -> atomicAdd
//   resolves it (rare: ~3% of cycles for N(0,1) data).
__global__ __launch_bounds__(BLOCK_THREADS, 7)
void hist_rows_kernel(const float* __restrict__ x, float* __restrict__ out) {
    __shared__ unsigned int priv[ROWS_PER_BLOCK][NBINS][32];

    const int warp = threadIdx.x >> 5;
    const int lane = threadIdx.x & 31;
    const int pair = warp >> 1;            // which row within the block
    const int half = warp & 1;             // which half of the row
    const int row  = blockIdx.x * ROWS_PER_BLOCK + pair;

    unsigned int (*h)[32] = priv[pair];

    // Zero: each warp of the pair clears half the bins of its lane column.
    #pragma unroll
    for (int b = 0; b < NBINS / 2; b++) h[half * (NBINS / 2) + b][lane] = 0u;
    __syncthreads();

    const float4* __restrict__ xr =
        (const float4*)(x + (size_t)row * ROW_LEN + (size_t)half * HALF_ROW);

    const float scale = 64.0f / 6.0f;   // NBINS / (VMAX - VMIN), fp32-rounded like ref

    // 4096 floats = 1024 float4 per warp; 32 float4 per lane; unroll 4 for MLP.
    #pragma unroll 1
    for (int it = 0; it < (HALF_ROW / 4) / 32; it += 4) {
        float4 v0 = xr[(it + 0) * 32 + lane];
        float4 v1 = xr[(it + 1) * 32 + lane];
        float4 v2 = xr[(it + 2) * 32 + lane];
        float4 v3 = xr[(it + 3) * 32 + lane];

        #pragma unroll
        for (int k = 0; k < 4; k++) {
            float4 v = (k == 0) ? v0 : (k == 1) ? v1 : (k == 2) ? v2 : v3;
            float f[4] = {v.x, v.y, v.z, v.w};
            #pragma unroll
            for (int j = 0; j < 4; j++) {
                // Exactly the reference fp32 sequence: (x - VMIN) then * scale,
                // floor (round toward -inf), clamp to [0, 63].
                int b = __float2int_rd(__fmul_rn(__fadd_rn(f[j], 3.0f), scale));
                b = max(0, min(NBINS - 1, b));
                atomicAdd(&h[b][lane], 1u);   // bank = lane, cross-warp safe
            }
        }
    }

    __syncthreads();

    // Reduce: warp0 of the pair handles bins [0,32), warp1 bins [32,64).
    // Rotated read (t+lane)&31 keeps banks distinct per lane on every step.
    const int bin = half * 32 + lane;
    unsigned int s = 0;
    #pragma unroll
    for (int t = 0; t < 32; t++) {
        s += h[bin][(t + lane) & 31];
    }

    const float inv_n = 1.0f / (float)ROW_LEN;
    out[(size_t)row * NBINS + bin] = (float)s * inv_n;
}

extern "C" void kernel_launch(void* const* d_in, const int* in_sizes, int n_in,
                              void* d_out, int out_size) {
    const float* x = (const float*)d_in[0];
    float* out = (float*)d_out;

    int nrows = in_sizes[0] / ROW_LEN;             // 4096
    int grid = nrows / ROWS_PER_BLOCK;             // 1024 blocks

    hist_rows_kernel<<<grid, BLOCK_THREADS>>>(x, out);
}

// round 3
// speedup vs baseline: 1.3887x; 1.1829x over previous
#include <cuda_runtime.h>

#define NBINS 64
#define ROW_LEN 8192
#define WARPS_PER_BLOCK 8          // 8 warps = 4 rows per block (2 warps/row)
#define ROWS_PER_BLOCK (WARPS_PER_BLOCK / 2)
#define BLOCK_THREADS (WARPS_PER_BLOCK * 32)
#define HALF_ROW (ROW_LEN / 2)     // 4096 elements per warp

// u16-packed per-lane-pair histograms in shared memory:
//   word = priv[pair][bin][lane & 15]; lane<16 uses low half, lane>=16 high half.
//   Max count per half = 2 warps x 128 elems/lane = 256 << 65536, so a plain
//   u32 atomicAdd of (1 or 1<<16) can never carry across halves.
//   16 KB smem/block -> 8 blocks/SM -> 64 warps (100% occ), and the whole
//   1024-block grid is resident in ONE wave (capacity 148*8 = 1184).
__global__ __launch_bounds__(BLOCK_THREADS, 8)
void hist_rows_kernel(const float* __restrict__ x, float* __restrict__ out) {
    __shared__ unsigned int priv[ROWS_PER_BLOCK][NBINS][16];

    const int warp = threadIdx.x >> 5;
    const int lane = threadIdx.x & 31;
    const int pair = warp >> 1;            // which row within the block
    const int half = warp & 1;             // which half of the row
    const int row  = blockIdx.x * ROWS_PER_BLOCK + pair;
    const int sub  = lane & 15;
    const unsigned int incr = (lane & 16) ? 0x10000u : 1u;

    unsigned int* slab = &priv[pair][0][0];   // NBINS*16 words

    // Zero all counters (4096 words / 256 threads = 16 each).
    unsigned int* flat = &priv[0][0][0];
    #pragma unroll
    for (int i = 0; i < (ROWS_PER_BLOCK * NBINS * 16) / BLOCK_THREADS; i++)
        flat[threadIdx.x + i * BLOCK_THREADS] = 0u;
    __syncthreads();

    const float4* __restrict__ xr =
        (const float4*)(x + (size_t)row * ROW_LEN + (size_t)half * HALF_ROW);

    const float scale = 64.0f / 6.0f;   // NBINS / (VMAX - VMIN), fp32-rounded like ref

    // 4096 floats = 1024 float4 per warp; 32 float4 per lane; unroll 4 for MLP.
    #pragma unroll 1
    for (int it = 0; it < (HALF_ROW / 4) / 32; it += 4) {
        float4 v0 = xr[(it + 0) * 32 + lane];
        float4 v1 = xr[(it + 1) * 32 + lane];
        float4 v2 = xr[(it + 2) * 32 + lane];
        float4 v3 = xr[(it + 3) * 32 + lane];

        #pragma unroll
        for (int k = 0; k < 4; k++) {
            float4 v = (k == 0) ? v0 : (k == 1) ? v1 : (k == 2) ? v2 : v3;
            float f[4] = {v.x, v.y, v.z, v.w};
            #pragma unroll
            for (int j = 0; j < 4; j++) {
                // Exactly the reference fp32 sequence: (x - VMIN) then * scale,
                // floor (round toward -inf), clamp to [0, 63].
                int b = __float2int_rd(__fmul_rn(__fadd_rn(f[j], 3.0f), scale));
                b = max(0, min(NBINS - 1, b));
                atomicAdd(&slab[b * 16 + sub], incr);   // worst case 2-way bank conflict
            }
        }
    }

    __syncthreads();

    // Reduce: warp0 of the pair handles bins [0,32), warp1 bins [32,64).
    // Each lane sums 16 packed words (lo+hi = 32 lane counts). Rotated word
    // index keeps reads spread across banks.
    const int bin = half * 32 + lane;
    unsigned int s = 0;
    #pragma unroll
    for (int t = 0; t < 16; t++) {
        unsigned int v = slab[bin * 16 + ((t + lane) & 15)];
        s += (v & 0xFFFFu) + (v >> 16);
    }

    const float inv_n = 1.0f / (float)ROW_LEN;
    out[(size_t)row * NBINS + bin] = (float)s * inv_n;
}

extern "C" void kernel_launch(void* const* d_in, const int* in_sizes, int n_in,
                              void* d_out, int out_size) {
    const float* x = (const float*)d_in[0];
    float* out = (float*)d_out;

    int nrows = in_sizes[0] / ROW_LEN;             // 4096
    int grid = nrows / ROWS_PER_BLOCK;             // 1024 blocks, single wave

    hist_rows_kernel<<<grid, BLOCK_THREADS>>>(x, out);
}